// round 1
// baseline (speedup 1.0000x reference)
#include <cuda_runtime.h>
#include <cuda_bf16.h>
#include <cstddef>

// RandCropResize: per-image crop [y1:y2, x1:x2] then bilinear resize back to
// (H, W) = (512, 512), align_corners=False. B=64, C=3, fp32.
//
// Mapping: block = (h, b), 512 threads along w. Each thread computes its
// source coords once and reuses them for the 3 channels. Writes are fully
// coalesced; gathers are near-coalesced because the resize is an upsample
// (source stride per output pixel = n/512 <= 1).

#define IMG_H 512
#define IMG_W 512
#define IMG_C 3

__global__ void __launch_bounds__(512, 4)
rand_crop_resize_kernel(const float* __restrict__ img,
                        const int* __restrict__ y1v,
                        const int* __restrict__ y2v,
                        const int* __restrict__ x1v,
                        const int* __restrict__ x2v,
                        float* __restrict__ out)
{
    const int h = blockIdx.x;     // output row
    const int b = blockIdx.y;     // batch
    const int w = threadIdx.x;    // output col

    const int Y1 = y1v[b], Y2 = y2v[b];
    const int X1 = x1v[b], X2 = x2v[b];

    // ---- vertical (y) source coords, align_corners=False ----
    const int   ncy = Y2 - Y1;
    const float ny  = (float)ncy;
    float sy = ((float)h + 0.5f) * ny * (1.0f / (float)IMG_H) - 0.5f;
    sy = fminf(fmaxf(sy, 0.0f), ny - 1.0f);
    const int   iy0 = (int)floorf(sy);
    const int   iy1 = min(iy0 + 1, ncy - 1);
    const float wy  = sy - (float)iy0;
    const int   ay0 = Y1 + iy0;
    const int   ay1 = Y1 + iy1;

    // ---- horizontal (x) source coords ----
    const int   ncx = X2 - X1;
    const float nx  = (float)ncx;
    float sx = ((float)w + 0.5f) * nx * (1.0f / (float)IMG_W) - 0.5f;
    sx = fminf(fmaxf(sx, 0.0f), nx - 1.0f);
    const int   ix0 = (int)floorf(sx);
    const int   ix1 = min(ix0 + 1, ncx - 1);
    const float wx  = sx - (float)ix0;
    const int   ax0 = X1 + ix0;
    const int   ax1 = X1 + ix1;

    const size_t img_stride = (size_t)IMG_H * IMG_W;
    const float* base  = img + (size_t)b * IMG_C * img_stride;
    float*       obase = out + (size_t)b * IMG_C * img_stride
                             + (size_t)h * IMG_W + w;

    const size_t r0off = (size_t)ay0 * IMG_W;
    const size_t r1off = (size_t)ay1 * IMG_W;

#pragma unroll
    for (int c = 0; c < IMG_C; c++) {
        const float* p = base + (size_t)c * img_stride;
        const float v00 = __ldg(p + r0off + ax0);
        const float v01 = __ldg(p + r0off + ax1);
        const float v10 = __ldg(p + r1off + ax0);
        const float v11 = __ldg(p + r1off + ax1);
        // y interpolation first (matches reference), then x
        const float row0 = v00 + (v10 - v00) * wy;
        const float row1 = v01 + (v11 - v01) * wy;
        obase[(size_t)c * img_stride] = row0 + (row1 - row0) * wx;
    }
}

extern "C" void kernel_launch(void* const* d_in, const int* in_sizes, int n_in,
                              void* d_out, int out_size)
{
    const float* img = (const float*)d_in[0];
    const int*   y1  = (const int*)d_in[1];
    const int*   y2  = (const int*)d_in[2];
    const int*   x1  = (const int*)d_in[3];
    const int*   x2  = (const int*)d_in[4];
    float*       out = (float*)d_out;

    dim3 grid(IMG_H, 64);   // (h, b)
    dim3 block(IMG_W);      // w
    rand_crop_resize_kernel<<<grid, block>>>(img, y1, y2, x1, x2, out);
}